// round 12
// baseline (speedup 1.0000x reference)
#include <cuda_runtime.h>

// Rayleigh-Bénard RHS, smem y/z-tiled.
// Block (32,8): tx = z float4-chunk (4 pts), ty = y row within 8-row tile.
// All 6 fields for y rows j-1..j+8 staged in 30KB smem; y-neighbors and
// z-halos from smem (no shuffles). x-neighbors from global (L1/L2).

#define NXg 256
#define NYg 256
#define NZg 128

__device__ __forceinline__ float4 operator+(float4 a, float4 b){return make_float4(a.x+b.x,a.y+b.y,a.z+b.z,a.w+b.w);}
__device__ __forceinline__ float4 operator-(float4 a, float4 b){return make_float4(a.x-b.x,a.y-b.y,a.z-b.z,a.w-b.w);}
__device__ __forceinline__ float4 operator*(float4 a, float4 b){return make_float4(a.x*b.x,a.y*b.y,a.z*b.z,a.w*b.w);}
__device__ __forceinline__ float4 operator*(float a, float4 b){return make_float4(a*b.x,a*b.y,a*b.z,a*b.w);}

// z first/second derivative for one float4 (4 consecutive z), halos prev/next.
// Wall one-sided stencils live inside lane0/lane31's own float4.
__device__ __forceinline__ float4 d1z4(float4 q, float prev, float next, int lane, float s) {
    float4 r;
    r.x = (lane == 0)  ? (-3.0f*q.x + 4.0f*q.y - q.z) * s : (q.y - prev) * s;
    r.y = (q.z - q.x) * s;
    r.z = (q.w - q.y) * s;
    r.w = (lane == 31) ? ( 3.0f*q.w - 4.0f*q.z + q.y) * s : (next - q.z) * s;
    return r;
}

__device__ __forceinline__ float4 d2z4(float4 q, float prev, float next, int lane, float s) {
    float4 r;
    r.x = (lane == 0)  ? (2.0f*q.x - 5.0f*q.y + 4.0f*q.z - q.w) * s : (prev - 2.0f*q.x + q.y) * s;
    r.y = (q.x - 2.0f*q.y + q.z) * s;
    r.z = (q.y - 2.0f*q.z + q.w) * s;
    r.w = (lane == 31) ? (2.0f*q.w - 5.0f*q.z + 4.0f*q.y - q.x) * s : (q.z - 2.0f*q.w + next) * s;
    return r;
}

__global__ __launch_bounds__(256)
void rbm_rhs_sm_kernel(const float* __restrict__ st, float* __restrict__ out) {
    const int tx = threadIdx.x;           // z chunk: points 4tx..4tx+3
    const int ty = threadIdx.y;           // local y row 0..7
    const int j0 = blockIdx.x * 8;        // y tile base
    const int i  = blockIdx.y;            // x

    constexpr int PL4 = NYg * NZg / 4;    // x stride, float4
    constexpr int NZ4 = NZg / 4;          // y stride, float4
    constexpr int FS4 = NXg * NYg * NZg / 4;

    constexpr float CP = 1004.0f, CVc = 717.0f, MU = 1.8e-5f, KTH = 0.025f, Gc = 9.8f;
    constexpr float Rg = CP - CVc;
    constexpr float INV2DX = 0.5f * NXg;
    constexpr float INV2DY = 0.5f * NYg;
    constexpr float INV2DZ = 0.5f * (NZg - 1);
    constexpr float INVDX2 = (float)NXg * NXg;
    constexpr float INVDY2 = (float)NYg * NYg;
    constexpr float INVDZ2 = (float)(NZg - 1) * (NZg - 1);

    // smem tile: 6 fields x 10 y-rows (j-1 .. j+8) x 128 z = 30 KB
    __shared__ float sm[6][10][NZg];

    const float4* S = (const float4*)st;
    float4* O = (float4*)out;

    // ---- cooperative fill: 1920 float4, coalesced (warp = one z-row) ----
    {
        const int tid = ty * 32 + tx;
        for (int idx = tid; idx < 6 * 10 * 32; idx += 256) {
            const int f   = idx / 320;
            const int rem = idx - f * 320;
            const int row = rem >> 5;          // 0..9
            const int t4  = rem & 31;          // float4 index in z
            const int jj  = (j0 + row - 1) & (NYg - 1);
            *(float4*)&sm[f][row][t4 * 4] = S[f * FS4 + i * PL4 + jj * NZ4 + t4];
        }
    }
    __syncthreads();

    const int j = j0 + ty;
    const int k0 = tx * 4;
    const int kp = (k0 == 0) ? 0 : k0 - 1;            // clamped z-halo idx (unused at wall)
    const int kn = (k0 == NZg - 4) ? NZg - 1 : k0 + 4;
    const bool wallLo = (tx == 0), wallHi = (tx == 31);

    const int c_i  = i * PL4 + j * NZ4 + tx;
    const int xp_i = ((i + 1) & (NXg - 1)) * PL4 + j * NZ4 + tx;
    const int xm_i = ((i - 1) & (NXg - 1)) * PL4 + j * NZ4 + tx;

    const int rc = ty + 1, rp = ty + 2, rm = ty;      // smem row indices

    // persistent centers (from smem)
    const float4 u   = *(const float4*)&sm[0][rc][k0];
    const float4 v   = *(const float4*)&sm[1][rc][k0];
    const float4 w   = *(const float4*)&sm[2][rc][k0];
    const float4 rou = *(const float4*)&sm[3][rc][k0];
    const float4 T   = *(const float4*)&sm[4][rc][k0];
    const float4 inv_rou = make_float4(1.0f/rou.x, 1.0f/rou.y, 1.0f/rou.z, 1.0f/rou.w);

    // ---------------- u section (+ dpdx, drou) ----------------
    {
        const float4 uxp = S[0*FS4 + xp_i];
        const float4 uxm = S[0*FS4 + xm_i];
        const float4 rxp = S[3*FS4 + xp_i];
        const float4 rxm = S[3*FS4 + xm_i];
        const float4 Txp = S[4*FS4 + xp_i];
        const float4 Txm = S[4*FS4 + xm_i];
        const float4 uyp = *(const float4*)&sm[0][rp][k0];
        const float4 uym = *(const float4*)&sm[0][rm][k0];
        const float u_prev = sm[0][rc][kp];
        const float u_next = sm[0][rc][kn];

        const float4 dpdx = (Rg * INV2DX) * (rxp * Txp - rxm * Txm);
        const float4 lap = INVDX2 * (uxp + uxm - 2.0f*u) + INVDY2 * (uyp + uym - 2.0f*u)
                         + d2z4(u, u_prev, u_next, tx, INVDZ2);
        const float4 adv = u * (INV2DX * (uxp - uxm)) + v * (INV2DY * (uyp - uym))
                         + w * d1z4(u, u_prev, u_next, tx, INV2DZ);
        float4 du = (MU * lap - dpdx) * inv_rou - adv;
        if (wallLo) du.x = 0.0f;
        if (wallHi) du.w = 0.0f;
        O[0*FS4 + c_i] = du;

        float4 drou = (-INV2DX) * (rxp * uxp - rxm * uxm);
        O[3*FS4 + c_i] = drou;
    }

    // ---------------- v section (+ dpdy) ----------------
    {
        const float4 vxp = S[1*FS4 + xp_i];
        const float4 vxm = S[1*FS4 + xm_i];
        const float4 vyp = *(const float4*)&sm[1][rp][k0];
        const float4 vym = *(const float4*)&sm[1][rm][k0];
        const float4 ryp = *(const float4*)&sm[3][rp][k0];
        const float4 rym = *(const float4*)&sm[3][rm][k0];
        const float4 Typ = *(const float4*)&sm[4][rp][k0];
        const float4 Tym = *(const float4*)&sm[4][rm][k0];
        const float v_prev = sm[1][rc][kp];
        const float v_next = sm[1][rc][kn];

        const float4 dpdy = (Rg * INV2DY) * (ryp * Typ - rym * Tym);
        const float4 lap = INVDX2 * (vxp + vxm - 2.0f*v) + INVDY2 * (vyp + vym - 2.0f*v)
                         + d2z4(v, v_prev, v_next, tx, INVDZ2);
        const float4 adv = u * (INV2DX * (vxp - vxm)) + v * (INV2DY * (vyp - vym))
                         + w * d1z4(v, v_prev, v_next, tx, INV2DZ);
        float4 dv = (MU * lap - dpdy) * inv_rou - adv;
        if (wallLo) dv.x = 0.0f;
        if (wallHi) dv.w = 0.0f;
        O[1*FS4 + c_i] = dv;
    }

    // ---------------- T section ----------------
    {
        const float4 Txp = S[4*FS4 + xp_i];
        const float4 Txm = S[4*FS4 + xm_i];
        const float4 Typ = *(const float4*)&sm[4][rp][k0];
        const float4 Tym = *(const float4*)&sm[4][rm][k0];
        const float T_prev = sm[4][rc][kp];
        const float T_next = sm[4][rc][kn];

        const float4 lap = INVDX2 * (Txp + Txm - 2.0f*T) + INVDY2 * (Typ + Tym - 2.0f*T)
                         + d2z4(T, T_prev, T_next, tx, INVDZ2);
        const float4 adv = u * (INV2DX * (Txp - Txm)) + v * (INV2DY * (Typ - Tym))
                         + w * d1z4(T, T_prev, T_next, tx, INV2DZ);
        float4 dT = (KTH / CVc) * (lap * inv_rou) - adv;
        if (wallLo) dT.x = 0.0f;
        if (wallHi) dT.w = 0.0f;
        O[4*FS4 + c_i] = dT;
    }

    // ---------------- w section (dpdz from smem rou,T column) ------------
    {
        const float4 wxp = S[2*FS4 + xp_i];
        const float4 wxm = S[2*FS4 + xm_i];
        const float4 wyp = *(const float4*)&sm[2][rp][k0];
        const float4 wym = *(const float4*)&sm[2][rm][k0];
        const float w_prev = sm[2][rc][kp];
        const float w_next = sm[2][rc][kn];

        const float4 p = Rg * (rou * T);
        const float p_prev = Rg * sm[3][rc][kp] * sm[4][rc][kp];
        const float p_next = Rg * sm[3][rc][kn] * sm[4][rc][kn];
        const float4 dpdz = d1z4(p, p_prev, p_next, tx, INV2DZ);

        const float4 lap = INVDX2 * (wxp + wxm - 2.0f*w) + INVDY2 * (wyp + wym - 2.0f*w)
                         + d2z4(w, w_prev, w_next, tx, INVDZ2);
        const float4 adv = u * (INV2DX * (wxp - wxm)) + v * (INV2DY * (wyp - wym))
                         + w * d1z4(w, w_prev, w_next, tx, INV2DZ);
        float4 dw = (MU * lap - dpdz - Gc * rou) * inv_rou - adv;
        if (wallLo) dw.x = 0.0f;
        if (wallHi) dw.w = 0.0f;
        O[2*FS4 + c_i] = dw;
    }

    // ---------------- c section ----------------
    {
        const float4 cxp = S[5*FS4 + xp_i];
        const float4 cxm = S[5*FS4 + xm_i];
        const float4 cc  = *(const float4*)&sm[5][rc][k0];
        const float4 cyp = *(const float4*)&sm[5][rp][k0];
        const float4 cym = *(const float4*)&sm[5][rm][k0];
        const float c_prev = sm[5][rc][kp];
        const float c_next = sm[5][rc][kn];

        const float4 adv = u * (INV2DX * (cxp - cxm)) + v * (INV2DY * (cyp - cym))
                         + w * d1z4(cc, c_prev, c_next, tx, INV2DZ);
        O[5*FS4 + c_i] = make_float4(-adv.x, -adv.y, -adv.z, -adv.w);
    }
}

extern "C" void kernel_launch(void* const* d_in, const int* in_sizes, int n_in,
                              void* d_out, int out_size) {
    const float* state = (const float*)d_in[0];
    float* out = (float*)d_out;
    dim3 block(32, 8);
    dim3 grid(NYg / 8, NXg);
    rbm_rhs_sm_kernel<<<grid, block>>>(state, out);
}

// round 13
// speedup vs baseline: 1.1427x; 1.1427x over previous
#include <cuda_runtime.h>

// Rayleigh-Bénard RHS, float4 along z, warp-specialized field groups.
// Block (32,4,2): tx=z float4-chunk (warp-uniform column), ty=field group,
// tz=local y row. Each warp computes 1-2 tendencies for its column ->
// short dependency chains (one load wave per warp) + low regs/thread.

#define NXg 256
#define NYg 256
#define NZg 128

__device__ __forceinline__ float4 operator+(float4 a, float4 b){return make_float4(a.x+b.x,a.y+b.y,a.z+b.z,a.w+b.w);}
__device__ __forceinline__ float4 operator-(float4 a, float4 b){return make_float4(a.x-b.x,a.y-b.y,a.z-b.z,a.w-b.w);}
__device__ __forceinline__ float4 operator*(float4 a, float4 b){return make_float4(a.x*b.x,a.y*b.y,a.z*b.z,a.w*b.w);}
__device__ __forceinline__ float4 operator*(float a, float4 b){return make_float4(a*b.x,a*b.y,a*b.z,a*b.w);}

__device__ __forceinline__ float4 d1z4(float4 q, float prev, float next, int lane, float s) {
    float4 r;
    r.x = (lane == 0)  ? (-3.0f*q.x + 4.0f*q.y - q.z) * s : (q.y - prev) * s;
    r.y = (q.z - q.x) * s;
    r.z = (q.w - q.y) * s;
    r.w = (lane == 31) ? ( 3.0f*q.w - 4.0f*q.z + q.y) * s : (next - q.z) * s;
    return r;
}

__device__ __forceinline__ float4 d2z4(float4 q, float prev, float next, int lane, float s) {
    float4 r;
    r.x = (lane == 0)  ? (2.0f*q.x - 5.0f*q.y + 4.0f*q.z - q.w) * s : (prev - 2.0f*q.x + q.y) * s;
    r.y = (q.x - 2.0f*q.y + q.z) * s;
    r.z = (q.y - 2.0f*q.z + q.w) * s;
    r.w = (lane == 31) ? (2.0f*q.w - 5.0f*q.z + 4.0f*q.y - q.x) * s : (q.z - 2.0f*q.w + next) * s;
    return r;
}

__global__ __launch_bounds__(256)
void rbm_rhs_ws_kernel(const float* __restrict__ st, float* __restrict__ out) {
    const int tx = threadIdx.x;                          // z chunk (lane)
    const int grp = threadIdx.y;                         // field group 0..3
    const int j = blockIdx.x * 2 + threadIdx.z;          // y
    const int i = blockIdx.y;                            // x

    constexpr int PL4 = NYg * NZg / 4;
    constexpr int NZ4 = NZg / 4;
    constexpr int FS4 = NXg * NYg * NZg / 4;

    constexpr float CP = 1004.0f, CVc = 717.0f, MU = 1.8e-5f, KTH = 0.025f, Gc = 9.8f;
    constexpr float Rg = CP - CVc;
    constexpr float INV2DX = 0.5f * NXg;
    constexpr float INV2DY = 0.5f * NYg;
    constexpr float INV2DZ = 0.5f * (NZg - 1);
    constexpr float INVDX2 = (float)NXg * NXg;
    constexpr float INVDY2 = (float)NYg * NYg;
    constexpr float INVDZ2 = (float)(NZg - 1) * (NZg - 1);

    const int c_i  = i * PL4 + j * NZ4 + tx;
    const int xp_i = ((i + 1) & (NXg - 1)) * PL4 + j * NZ4 + tx;
    const int xm_i = ((i - 1) & (NXg - 1)) * PL4 + j * NZ4 + tx;
    const int yp_i = i * PL4 + ((j + 1) & (NYg - 1)) * NZ4 + tx;
    const int ym_i = i * PL4 + ((j - 1) & (NYg - 1)) * NZ4 + tx;

    const float4* S = (const float4*)st;
    float4* O = (float4*)out;
    const unsigned FULL = 0xFFFFFFFFu;
    const bool wallLo = (tx == 0), wallHi = (tx == 31);

    if (grp == 0) {
        // ---------- du + drou ----------
        const float4 uxp = S[0*FS4 + xp_i];
        const float4 uxm = S[0*FS4 + xm_i];
        const float4 uyp = S[0*FS4 + yp_i];
        const float4 uym = S[0*FS4 + ym_i];
        const float4 rxp = S[3*FS4 + xp_i];
        const float4 rxm = S[3*FS4 + xm_i];
        const float4 Txp = S[4*FS4 + xp_i];
        const float4 Txm = S[4*FS4 + xm_i];
        const float4 u   = S[0*FS4 + c_i];
        const float4 v   = S[1*FS4 + c_i];
        const float4 w   = S[2*FS4 + c_i];
        const float4 rou = S[3*FS4 + c_i];

        const float u_prev = __shfl_up_sync(FULL, u.w, 1);
        const float u_next = __shfl_down_sync(FULL, u.x, 1);
        const float4 inv_rou = make_float4(1.0f/rou.x, 1.0f/rou.y, 1.0f/rou.z, 1.0f/rou.w);

        const float4 dpdx = (Rg * INV2DX) * (rxp * Txp - rxm * Txm);
        const float4 lap = INVDX2 * (uxp + uxm - 2.0f*u) + INVDY2 * (uyp + uym - 2.0f*u)
                         + d2z4(u, u_prev, u_next, tx, INVDZ2);
        const float4 adv = u * (INV2DX * (uxp - uxm)) + v * (INV2DY * (uyp - uym))
                         + w * d1z4(u, u_prev, u_next, tx, INV2DZ);
        float4 du = (MU * lap - dpdx) * inv_rou - adv;
        if (wallLo) du.x = 0.0f;
        if (wallHi) du.w = 0.0f;
        O[0*FS4 + c_i] = du;

        float4 drou = (-INV2DX) * (rxp * uxp - rxm * uxm);
        O[3*FS4 + c_i] = drou;
    }
    else if (grp == 1) {
        // ---------- dv ----------
        const float4 vxp = S[1*FS4 + xp_i];
        const float4 vxm = S[1*FS4 + xm_i];
        const float4 vyp = S[1*FS4 + yp_i];
        const float4 vym = S[1*FS4 + ym_i];
        const float4 ryp = S[3*FS4 + yp_i];
        const float4 rym = S[3*FS4 + ym_i];
        const float4 Typ = S[4*FS4 + yp_i];
        const float4 Tym = S[4*FS4 + ym_i];
        const float4 u   = S[0*FS4 + c_i];
        const float4 v   = S[1*FS4 + c_i];
        const float4 w   = S[2*FS4 + c_i];
        const float4 rou = S[3*FS4 + c_i];

        const float v_prev = __shfl_up_sync(FULL, v.w, 1);
        const float v_next = __shfl_down_sync(FULL, v.x, 1);
        const float4 inv_rou = make_float4(1.0f/rou.x, 1.0f/rou.y, 1.0f/rou.z, 1.0f/rou.w);

        const float4 dpdy = (Rg * INV2DY) * (ryp * Typ - rym * Tym);
        const float4 lap = INVDX2 * (vxp + vxm - 2.0f*v) + INVDY2 * (vyp + vym - 2.0f*v)
                         + d2z4(v, v_prev, v_next, tx, INVDZ2);
        const float4 adv = u * (INV2DX * (vxp - vxm)) + v * (INV2DY * (vyp - vym))
                         + w * d1z4(v, v_prev, v_next, tx, INV2DZ);
        float4 dv = (MU * lap - dpdy) * inv_rou - adv;
        if (wallLo) dv.x = 0.0f;
        if (wallHi) dv.w = 0.0f;
        O[1*FS4 + c_i] = dv;
    }
    else if (grp == 2) {
        // ---------- dT + dc ----------
        const float4 Txp = S[4*FS4 + xp_i];
        const float4 Txm = S[4*FS4 + xm_i];
        const float4 Typ = S[4*FS4 + yp_i];
        const float4 Tym = S[4*FS4 + ym_i];
        const float4 u   = S[0*FS4 + c_i];
        const float4 v   = S[1*FS4 + c_i];
        const float4 w   = S[2*FS4 + c_i];
        const float4 rou = S[3*FS4 + c_i];
        const float4 T   = S[4*FS4 + c_i];

        {
            const float T_prev = __shfl_up_sync(FULL, T.w, 1);
            const float T_next = __shfl_down_sync(FULL, T.x, 1);
            const float4 inv_rou = make_float4(1.0f/rou.x, 1.0f/rou.y, 1.0f/rou.z, 1.0f/rou.w);

            const float4 lap = INVDX2 * (Txp + Txm - 2.0f*T) + INVDY2 * (Typ + Tym - 2.0f*T)
                             + d2z4(T, T_prev, T_next, tx, INVDZ2);
            const float4 adv = u * (INV2DX * (Txp - Txm)) + v * (INV2DY * (Typ - Tym))
                             + w * d1z4(T, T_prev, T_next, tx, INV2DZ);
            float4 dT = (KTH / CVc) * (lap * inv_rou) - adv;
            if (wallLo) dT.x = 0.0f;
            if (wallHi) dT.w = 0.0f;
            O[4*FS4 + c_i] = dT;
        }
        {
            const float4 cxp = S[5*FS4 + xp_i];
            const float4 cxm = S[5*FS4 + xm_i];
            const float4 cyp = S[5*FS4 + yp_i];
            const float4 cym = S[5*FS4 + ym_i];
            const float4 cc  = S[5*FS4 + c_i];
            const float c_prev = __shfl_up_sync(FULL, cc.w, 1);
            const float c_next = __shfl_down_sync(FULL, cc.x, 1);

            const float4 adv = u * (INV2DX * (cxp - cxm)) + v * (INV2DY * (cyp - cym))
                             + w * d1z4(cc, c_prev, c_next, tx, INV2DZ);
            O[5*FS4 + c_i] = make_float4(-adv.x, -adv.y, -adv.z, -adv.w);
        }
    }
    else {
        // ---------- dw (dpdz via shuffles of p) ----------
        const float4 wxp = S[2*FS4 + xp_i];
        const float4 wxm = S[2*FS4 + xm_i];
        const float4 wyp = S[2*FS4 + yp_i];
        const float4 wym = S[2*FS4 + ym_i];
        const float4 u   = S[0*FS4 + c_i];
        const float4 v   = S[1*FS4 + c_i];
        const float4 w   = S[2*FS4 + c_i];
        const float4 rou = S[3*FS4 + c_i];
        const float4 T   = S[4*FS4 + c_i];

        const float w_prev = __shfl_up_sync(FULL, w.w, 1);
        const float w_next = __shfl_down_sync(FULL, w.x, 1);
        const float4 inv_rou = make_float4(1.0f/rou.x, 1.0f/rou.y, 1.0f/rou.z, 1.0f/rou.w);

        const float4 p = Rg * (rou * T);
        const float p_prev = __shfl_up_sync(FULL, p.w, 1);
        const float p_next = __shfl_down_sync(FULL, p.x, 1);
        const float4 dpdz = d1z4(p, p_prev, p_next, tx, INV2DZ);

        const float4 lap = INVDX2 * (wxp + wxm - 2.0f*w) + INVDY2 * (wyp + wym - 2.0f*w)
                         + d2z4(w, w_prev, w_next, tx, INVDZ2);
        const float4 adv = u * (INV2DX * (wxp - wxm)) + v * (INV2DY * (wyp - wym))
                         + w * d1z4(w, w_prev, w_next, tx, INV2DZ);
        float4 dw = (MU * lap - dpdz - Gc * rou) * inv_rou - adv;
        if (wallLo) dw.x = 0.0f;
        if (wallHi) dw.w = 0.0f;
        O[2*FS4 + c_i] = dw;
    }
}

extern "C" void kernel_launch(void* const* d_in, const int* in_sizes, int n_in,
                              void* d_out, int out_size) {
    const float* state = (const float*)d_in[0];
    float* out = (float*)d_out;
    dim3 block(32, 4, 2);                 // lane=z, ty=field group, tz=y row
    dim3 grid(NYg / 2, NXg);
    rbm_rhs_ws_kernel<<<grid, block>>>(state, out);
}